// round 13
// baseline (speedup 1.0000x reference)
#include <cuda_runtime.h>
#include <math.h>

// Problem constants
#define TT      4096
#define HH      1024
#define NH      16
#define HD      64
#define II      4096
#define VV      1024
#define NSTEPS  8
#define EPSF    1e-6f
#define THETAF  10000.0f

// ---------------------------------------------------------------------------
// Scratch (device globals -- verified working in R11)
// ---------------------------------------------------------------------------
__device__ float g_hcur  [TT * HH];
__device__ float g_x     [TT * HH];
__device__ float g_q     [TT * HH];
__device__ float g_k     [TT * HH];
__device__ float g_v     [TT * HH];
__device__ float g_ctx   [TT * HH];
__device__ float g_hattn [TT * HH];
__device__ float g_g     [TT * II];
__device__ float g_u     [TT * II];
__device__ float g_logits[TT * VV];
__device__ float g_kcache[(size_t)TT * NH * NSTEPS * HD];
__device__ float g_vcache[(size_t)TT * NH * NSTEPS * HD];

#define SB_HCUR   0
#define SB_X      1
#define SB_Q      2
#define SB_K      3
#define SB_V      4
#define SB_CTX    5
#define SB_HATTN  6
#define SB_G      7
#define SB_U      8
#define SB_LOGITS 9

__device__ __forceinline__ float* sel_buf(int s) {
    switch (s) {
        case SB_HCUR:  return g_hcur;
        case SB_X:     return g_x;
        case SB_Q:     return g_q;
        case SB_K:     return g_k;
        case SB_V:     return g_v;
        case SB_CTX:   return g_ctx;
        case SB_HATTN: return g_hattn;
        case SB_G:     return g_g;
        case SB_U:     return g_u;
        default:       return g_logits;
    }
}

// ---------------------------------------------------------------------------
__global__ void copy_in_kernel(const float* __restrict__ src, int n4) {
    int i = blockIdx.x * blockDim.x + threadIdx.x;
    if (i < n4) {
        reinterpret_cast<float4*>(g_hcur)[i] = reinterpret_cast<const float4*>(src)[i];
    }
}

// ---------------------------------------------------------------------------
__global__ void rmsnorm_kernel(int src_sel, const float* __restrict__ w) {
    const float* in = sel_buf(src_sel);
    int t = blockIdx.x;
    int tid = threadIdx.x;
    float4 vv = reinterpret_cast<const float4*>(in + (size_t)t * HH)[tid];
    float ss = vv.x * vv.x + vv.y * vv.y + vv.z * vv.z + vv.w * vv.w;
    #pragma unroll
    for (int o = 16; o > 0; o >>= 1) ss += __shfl_xor_sync(0xffffffffu, ss, o);
    __shared__ float warp_ss[8];
    int wid = tid >> 5, lane = tid & 31;
    if (lane == 0) warp_ss[wid] = ss;
    __syncthreads();
    if (wid == 0) {
        float s = (lane < 8) ? warp_ss[lane] : 0.0f;
        #pragma unroll
        for (int o = 4; o > 0; o >>= 1) s += __shfl_xor_sync(0xffffffffu, s, o);
        if (lane == 0) warp_ss[0] = s;
    }
    __syncthreads();
    float scale = rsqrtf(warp_ss[0] * (1.0f / HH) + EPSF);
    const float4 w4 = reinterpret_cast<const float4*>(w)[tid];
    float4 o4;
    o4.x = vv.x * scale * w4.x;
    o4.y = vv.y * scale * w4.y;
    o4.z = vv.z * scale * w4.z;
    o4.w = vv.w * scale * w4.w;
    reinterpret_cast<float4*>(g_x + (size_t)t * HH)[tid] = o4;
}

// ---------------------------------------------------------------------------
// SGEMM: C[M,N] = A[M,K] * B[K,N] (+resid) (+bias).
// BM=BN=128, BK=8, 256 threads, 8x8 per thread. Verified vs host in R11.
// ---------------------------------------------------------------------------
template <int RESID, int BIAS>
__global__ __launch_bounds__(256, 2)
void sgemm_kernel(int asel, const float* __restrict__ B, int csel, int rsel,
                  const float* __restrict__ bias, int M, int N, int K) {
    const float* A  = sel_buf(asel);
    float*       C  = sel_buf(csel);
    const float* Rp = RESID ? sel_buf(rsel) : (const float*)0;

    __shared__ float As[8][132];
    __shared__ float Bs[8][128];

    const int bx = blockIdx.x, by = blockIdx.y;
    const int tid = threadIdx.x;
    const int tx = tid & 15;
    const int ty = tid >> 4;

    float acc[8][8];
    #pragma unroll
    for (int i = 0; i < 8; i++)
        #pragma unroll
        for (int j = 0; j < 8; j++) acc[i][j] = 0.0f;

    const int arow = tid >> 1;
    const int acol = (tid & 1) * 4;
    const int brow = tid >> 5;
    const int bcol = (tid & 31) * 4;

    const float* Aptr = A + (size_t)(by * 128 + arow) * K + acol;
    const float* Bptr = B + (size_t)brow * N + bx * 128 + bcol;

    for (int k0 = 0; k0 < K; k0 += 8) {
        float4 a4 = *reinterpret_cast<const float4*>(Aptr + k0);
        float4 b4 = *reinterpret_cast<const float4*>(Bptr + (size_t)k0 * N);
        As[acol + 0][arow] = a4.x;
        As[acol + 1][arow] = a4.y;
        As[acol + 2][arow] = a4.z;
        As[acol + 3][arow] = a4.w;
        *reinterpret_cast<float4*>(&Bs[brow][bcol]) = b4;
        __syncthreads();
        #pragma unroll
        for (int kk = 0; kk < 8; kk++) {
            float4 a0 = *reinterpret_cast<const float4*>(&As[kk][ty * 8]);
            float4 a1 = *reinterpret_cast<const float4*>(&As[kk][ty * 8 + 4]);
            float4 b0 = *reinterpret_cast<const float4*>(&Bs[kk][tx * 8]);
            float4 b1 = *reinterpret_cast<const float4*>(&Bs[kk][tx * 8 + 4]);
            float ar[8] = {a0.x, a0.y, a0.z, a0.w, a1.x, a1.y, a1.z, a1.w};
            float br[8] = {b0.x, b0.y, b0.z, b0.w, b1.x, b1.y, b1.z, b1.w};
            #pragma unroll
            for (int i = 0; i < 8; i++)
                #pragma unroll
                for (int j = 0; j < 8; j++)
                    acc[i][j] = fmaf(ar[i], br[j], acc[i][j]);
        }
        __syncthreads();
    }

    #pragma unroll
    for (int i = 0; i < 8; i++) {
        int row = by * 128 + ty * 8 + i;
        #pragma unroll
        for (int j = 0; j < 8; j += 4) {
            int col = bx * 128 + tx * 8 + j;
            size_t idx = (size_t)row * N + col;
            float4 r;
            r.x = acc[i][j + 0]; r.y = acc[i][j + 1];
            r.z = acc[i][j + 2]; r.w = acc[i][j + 3];
            if (RESID) {
                float4 rr = *reinterpret_cast<const float4*>(Rp + idx);
                r.x += rr.x; r.y += rr.y; r.z += rr.z; r.w += rr.w;
            }
            if (BIAS) {
                float4 bb = *reinterpret_cast<const float4*>(bias + col);
                r.x += bb.x; r.y += bb.y; r.z += bb.z; r.w += bb.w;
            }
            *reinterpret_cast<float4*>(C + idx) = r;
        }
    }
}

// ---------------------------------------------------------------------------
__global__ void qkv_post_kernel(int p) {
    int t = blockIdx.x;
    int head = threadIdx.x >> 5;
    int i = threadIdx.x & 31;
    size_t base = (size_t)t * HH + head * HD;
    float invf = 1.0f / powf(THETAF, (2.0f * (float)i) / (float)HD);
    float ang = (float)p * invf;
    float c = cosf(ang), s = sinf(ang);

    float x1 = g_q[base + i], x2 = g_q[base + i + 32];
    g_q[base + i]      = x1 * c - x2 * s;
    g_q[base + i + 32] = x2 * c + x1 * s;

    size_t cb = (((size_t)t * NH + head) * NSTEPS + p) * HD;
    x1 = g_k[base + i]; x2 = g_k[base + i + 32];
    g_kcache[cb + i]      = x1 * c - x2 * s;
    g_kcache[cb + i + 32] = x2 * c + x1 * s;

    g_vcache[cb + i]      = g_v[base + i];
    g_vcache[cb + i + 32] = g_v[base + i + 32];
}

// ---------------------------------------------------------------------------
__global__ void attn_kernel(int p) {
    int gw = (blockIdx.x * blockDim.x + threadIdx.x) >> 5;
    int lane = threadIdx.x & 31;
    int t = gw / NH, head = gw % NH;

    float2 q2 = *reinterpret_cast<const float2*>(g_q + (size_t)t * HH + head * HD + lane * 2);
    size_t cbase = ((size_t)t * NH + head) * NSTEPS * HD;

    float sc[NSTEPS];
    float mx = -1e30f;
    for (int m = 0; m <= p; m++) {
        float2 k2 = *reinterpret_cast<const float2*>(g_kcache + cbase + m * HD + lane * 2);
        float d = q2.x * k2.x + q2.y * k2.y;
        #pragma unroll
        for (int o = 16; o > 0; o >>= 1) d += __shfl_xor_sync(0xffffffffu, d, o);
        d *= 0.125f;
        sc[m] = d;
        mx = fmaxf(mx, d);
    }
    float sum = 0.0f;
    for (int m = 0; m <= p; m++) { sc[m] = expf(sc[m] - mx); sum += sc[m]; }
    float inv = 1.0f / sum;
    float cx = 0.0f, cy = 0.0f;
    for (int m = 0; m <= p; m++) {
        float2 v2 = *reinterpret_cast<const float2*>(g_vcache + cbase + m * HD + lane * 2);
        float w = sc[m] * inv;
        cx = fmaf(w, v2.x, cx);
        cy = fmaf(w, v2.y, cy);
    }
    float2 o2; o2.x = cx; o2.y = cy;
    *reinterpret_cast<float2*>(g_ctx + (size_t)t * HH + head * HD + lane * 2) = o2;
}

// ---------------------------------------------------------------------------
__global__ void silu_mul_kernel(int n) {
    int i = blockIdx.x * blockDim.x + threadIdx.x;
    if (i < n) {
        float gv = g_g[i];
        float sv = gv / (1.0f + expf(-gv));
        g_g[i] = sv * g_u[i];
    }
}

// ---------------------------------------------------------------------------
// Argmax over g_logits row (first-occurrence ties; non-finite skipped),
// emit token AS FLOAT32 (the comparison dtype), g_hcur <- E[tok].
// One block per t, 256 threads.
// ---------------------------------------------------------------------------
__global__ void argmax_embed_kernel(const float* __restrict__ E,
                                    float* __restrict__ out, int p) {
    int t = blockIdx.x;
    int tid = threadIdx.x;
    const float* row = g_logits + (size_t)t * VV;
    float bv = -3.402823466e+38f;
    int bi = 0;
    for (int j = tid; j < VV; j += 256) {
        float vv = row[j];
        if (!isfinite(vv)) continue;
        if (vv > bv || (vv == bv && j < bi)) { bv = vv; bi = j; }
    }
    __shared__ float sv[256];
    __shared__ int   si[256];
    sv[tid] = bv; si[tid] = bi;
    __syncthreads();
    for (int s = 128; s > 0; s >>= 1) {
        if (tid < s) {
            if (sv[tid + s] > sv[tid] ||
                (sv[tid + s] == sv[tid] && si[tid + s] < si[tid])) {
                sv[tid] = sv[tid + s]; si[tid] = si[tid + s];
            }
        }
        __syncthreads();
    }
    int tok = si[0];
    tok = (tok < 0) ? 0 : ((tok >= VV) ? (VV - 1) : tok);
    if (tid == 0) out[(size_t)t * NSTEPS + p] = (float)tok;   // FLOAT value
    const float4* erow = reinterpret_cast<const float4*>(E + (size_t)tok * HH);
    reinterpret_cast<float4*>(g_hcur + (size_t)t * HH)[tid] = erow[tid];
}

// ---------------------------------------------------------------------------
// Host driver. Dict input order (R11-verified). Graph-capturable:
// kernel launches only.
// ---------------------------------------------------------------------------
static void launch_sgemm(int asel, const float* B, int csel, int rsel,
                         const float* bias, int M, int N, int K) {
    dim3 grid(N / 128, M / 128), block(256);
    if (rsel >= 0)   sgemm_kernel<1, 0><<<grid, block>>>(asel, B, csel, rsel, (const float*)0, M, N, K);
    else if (bias)   sgemm_kernel<0, 1><<<grid, block>>>(asel, B, csel, 0, bias, M, N, K);
    else             sgemm_kernel<0, 0><<<grid, block>>>(asel, B, csel, 0, (const float*)0, M, N, K);
}

extern "C" void kernel_launch(void* const* d_in, const int* in_sizes, int n_in,
                              void* d_out, int out_size) {
    const float* in_h = (const float*)d_in[0];   // chunk_hidden_states (1,T,H)
    const float* Wq   = (const float*)d_in[1];
    const float* Wk   = (const float*)d_in[2];
    const float* Wv   = (const float*)d_in[3];
    const float* Wo   = (const float*)d_in[4];
    const float* Wg   = (const float*)d_in[5];
    const float* Wu   = (const float*)d_in[6];
    const float* Wd   = (const float*)d_in[7];
    const float* n1   = (const float*)d_in[8];
    const float* n2   = (const float*)d_in[9];
    const float* E    = (const float*)d_in[10];
    const float* Wout = (const float*)d_in[11];
    const float* bout = (const float*)d_in[12];
    float* out = (float*)d_out;   // FLOAT32 token values (32768 elements)

    // h_cur <- x0
    {
        int n4 = TT * HH / 4;
        copy_in_kernel<<<(n4 + 255) / 256, 256>>>(in_h, n4);
    }

    for (int p = 0; p < NSTEPS; p++) {
        // x = rmsnorm(h_cur, n1)
        rmsnorm_kernel<<<TT, 256>>>(SB_HCUR, n1);
        // q,k,v projections for the new position (KV cache)
        launch_sgemm(SB_X, Wq, SB_Q, -1, (const float*)0, TT, HH, HH);
        launch_sgemm(SB_X, Wk, SB_K, -1, (const float*)0, TT, HH, HH);
        launch_sgemm(SB_X, Wv, SB_V, -1, (const float*)0, TT, HH, HH);
        // RoPE(q); RoPE(k)->cache; v->cache
        qkv_post_kernel<<<TT, NH * 32>>>(p);
        // attention over cache (<= p+1 keys)
        attn_kernel<<<TT * NH / 8, 256>>>(p);
        // h_attn = h_cur + ctx @ Wo
        launch_sgemm(SB_CTX, Wo, SB_HATTN, SB_HCUR, (const float*)0, TT, HH, HH);
        // x = rmsnorm(h_attn, n2)
        rmsnorm_kernel<<<TT, 256>>>(SB_HATTN, n2);
        // MLP
        launch_sgemm(SB_X, Wg, SB_G, -1, (const float*)0, TT, II, HH);
        launch_sgemm(SB_X, Wu, SB_U, -1, (const float*)0, TT, II, HH);
        {
            int n = TT * II;
            silu_mul_kernel<<<(n + 255) / 256, 256>>>(n);
        }
        // h_new = h_attn + act @ Wd  (into hcur)
        launch_sgemm(SB_G, Wd, SB_HCUR, SB_HATTN, (const float*)0, TT, HH, II);
        // logits = h_new @ Wout + bout
        launch_sgemm(SB_HCUR, Wout, SB_LOGITS, -1, bout, TT, VV, HH);
        // argmax -> token (float32); h_cur <- E[token]
        argmax_embed_kernel<<<TT, 256>>>(E, out, p);
    }
}